// round 15
// baseline (speedup 1.0000x reference)
#include <cuda_runtime.h>
#include <cuda.h>
#include <cuda_bf16.h>
#include <math.h>
#include <stdint.h>

// Problem constants
#define B_   128
#define S_   256
#define D_   1024
#define K_   8
#define L_   2

// -------- scratch (no allocations allowed) --------
__device__ uint16_t g_Wb [(size_t)256 * D_];   // packed weights q|k|v|mi, bf16
__device__ float    g_Ymi [(size_t)512 * 64];  // mi projections
__device__ int      g_miDone;                  // mi-completion counter

__device__ __forceinline__ uint2 f4_to_bf4(float4 v) {
    __nv_bfloat162 lo = __floats2bfloat162_rn(v.x, v.y);
    __nv_bfloat162 hi = __floats2bfloat162_rn(v.z, v.w);
    uint2 r;
    r.x = *reinterpret_cast<uint32_t*>(&lo);
    r.y = *reinterpret_cast<uint32_t*>(&hi);
    return r;
}

// =====================================================================
// Kernel 1: weight pack (32 blocks x 512) + flag reset
// =====================================================================
__global__ void __launch_bounds__(512)
wpack_kernel(const float* __restrict__ wq, const float* __restrict__ wk,
             const float* __restrict__ wv, const float* __restrict__ wmi)
{
    if (blockIdx.x == 0 && threadIdx.x == 0) g_miDone = 0;
    int f4base = blockIdx.x * 2048 + threadIdx.x;
    #pragma unroll
    for (int i = 0; i < 4; i++) {
        int f4 = f4base + i * 512;            // 0..65535
        int wsel = f4 >> 14;
        const float* W = (wsel == 0) ? wq : (wsel == 1) ? wk :
                         (wsel == 2) ? wv : wmi;
        float4 v = reinterpret_cast<const float4*>(W)[f4 & 16383];
        reinterpret_cast<uint2*>(g_Wb)[f4] = f4_to_bf4(v);
    }
}

// =====================================================================
// Kernel 2: FULLY FUSED gather + GEMM + head.
//  blocks 0..15  : mi — gather+pool 16 bs each, 32x64 GEMM -> g_Ymi, flag
//  blocks 16..143: qkv — inline-gathered 32x192 GEMM + head (b = bid-16)
// =====================================================================
#define QA_BUF 4096                    // 32 rows x 128B (one stage)
#define QB_OFF (2 * QA_BUF)            // 8192
#define QB_ST  24576                   // 192 rows x 128B
#define MA_FULL 65536                  // 32 rows x 16 stages x 128B
#define MB_ST  8192                    // 64 rows x 128B
#define DSMEM  (MA_FULL + 3 * MB_ST)   // 90112 (covers qkv's 81920 too)

#define PS 68

__device__ __forceinline__ void mbar_wait(uint32_t mbar, int phase) {
    asm volatile(
        "{\n\t.reg .pred P;\n"
        "W%=:\n\t"
        "mbarrier.try_wait.parity.acquire.cta.shared::cta.b64 P, [%0], %1, 0x989680;\n\t"
        "@P bra D%=;\n\t"
        "bra W%=;\n"
        "D%=:\n\t}"
        :: "r"(mbar), "r"(phase) : "memory");
}

__device__ __forceinline__ void tma_2d(uint32_t dst, const CUtensorMap* tm,
                                       int x, int y, uint32_t mbar) {
    asm volatile(
        "cp.async.bulk.tensor.2d.shared::cta.global.tile.mbarrier::complete_tx::bytes "
        "[%0], [%1, {%2, %3}], [%4];"
        :: "r"(dst), "l"(tm), "r"(x), "r"(y), "r"(mbar) : "memory");
}

#define LDMX4(dst, addr) \
    asm volatile("ldmatrix.sync.aligned.m8n8.x4.shared.b16 {%0,%1,%2,%3}, [%4];" \
                 : "=r"((dst)[0]), "=r"((dst)[1]), "=r"((dst)[2]), "=r"((dst)[3]) : "r"(addr))

#define MMA16816(c, a, b0r, b1r) \
    asm volatile("mma.sync.aligned.m16n8k16.row.col.f32.bf16.bf16.f32 " \
                 "{%0,%1,%2,%3}, {%4,%5,%6,%7}, {%8,%9}, {%0,%1,%2,%3};" \
                 : "+f"((c)[0]), "+f"((c)[1]), "+f"((c)[2]), "+f"((c)[3]) \
                 : "r"((a)[0]), "r"((a)[1]), "r"((a)[2]), "r"((a)[3]), \
                   "r"(b0r), "r"(b1r))

__device__ __forceinline__ float gelu_f(float x) {
    return 0.5f * x * (1.0f + erff(x * 0.70710678118654752440f));
}
__device__ __forceinline__ float4 fma4(float4 a, float4 b, float4 c) {
    return make_float4(fmaf(a.x,b.x,c.x), fmaf(a.y,b.y,c.y),
                       fmaf(a.z,b.z,c.z), fmaf(a.w,b.w,c.w));
}
__device__ __forceinline__ float hsum4(float4 a) { return (a.x+a.y)+(a.z+a.w); }

__global__ void __launch_bounds__(256, 1)
fused_kernel(const __grid_constant__ CUtensorMap tmW192,
             const __grid_constant__ CUtensorMap tmW64,
             const float* __restrict__ token,
             const int* __restrict__ kw_idx,
             const float* __restrict__ q_b, const float* __restrict__ k_b,
             const float* __restrict__ v_b, const float* __restrict__ mi_b,
             const float* __restrict__ inter_w, const float* __restrict__ inter_b,
             const float* __restrict__ fc0_w, const float* __restrict__ fc0_b,
             const float* __restrict__ fc1_w, const float* __restrict__ fc1_b,
             float* __restrict__ out)
{
    extern __shared__ __align__(1024) uint16_t smem_b[];
    __shared__ __align__(8) uint64_t mbar_s[6];
    __shared__ uint32_t rowOff[256];       // token row offsets (elements)
    __shared__ __align__(16) float hbuf[6 * 16 * PS];
    __shared__ __align__(16) float e1s[16*PS], e2s[16*PS];
    __shared__ __align__(16) float att[512];
    __shared__ __align__(16) float sv[4][64];
    __shared__ __align__(16) float aV[4][64];
    __shared__ __align__(16) float feat[520];
    __shared__ float h1[64];

    const uint32_t smem_s = (uint32_t)__cvta_generic_to_shared(smem_b);
    const uint32_t mb     = (uint32_t)__cvta_generic_to_shared(mbar_s);

    const int tid  = threadIdx.x;
    const int lane = tid & 31;
    const int warp = tid >> 5;
    const bool isMi = (blockIdx.x < 16);

    if (tid == 0) {
        #pragma unroll
        for (int s = 0; s < 3; s++) {
            asm volatile("mbarrier.init.shared.b64 [%0], %1;" :: "r"(mb + s * 8), "r"(1) : "memory");
            asm volatile("mbarrier.init.shared.b64 [%0], %1;" :: "r"(mb + 24 + s * 8), "r"(256) : "memory");
        }
    }

    const int j4 = lane >> 3;
    const int lr = lane & 7;
    const int g  = lane >> 2;
    const int tg = lane & 3;

    if (isMi) {
        // ========== mi: gather+pool 16 bs, then 32x64x1024 GEMM ==========
        // row offsets for 16 bs x 16 rows
        {
            int bsl = tid >> 4, r = tid & 15;
            int bs = blockIdx.x * 16 + bsl;
            int b = bs >> 1, s = bs & 1;
            int l = r >> 3, k = r & 7;
            int ii = kw_idx[(b * 2 + (1 - s)) * K_ + k];
            rowOff[tid] = (uint32_t)((((b * 2 + s) * 2 + l) * S_ + ii) * D_);
        }
        __syncthreads();

        // B ring prologue (overlaps pooling)
        if (tid == 0) {
            #pragma unroll
            for (int s = 0; s < 3; s++) {
                uint32_t fb = mb + s * 8;
                asm volatile("mbarrier.arrive.expect_tx.shared.b64 _, [%0], %1;"
                             :: "r"(fb), "r"(MB_ST) : "memory");
                tma_2d(smem_s + MA_FULL + s * MB_ST, &tmW64, s * 64, 192, fb);
            }
        }

        // pooling: warp w handles bs_local 2w, 2w+1
        #pragma unroll
        for (int bi = 0; bi < 2; bi++) {
            int bsl = warp * 2 + bi;
            const uint32_t* ro = rowOff + bsl * 16;
            #pragma unroll
            for (int pos = 0; pos < 8; pos++) {
                int c = pos * 32 + lane;          // float4 column 0..255
                float4 mx = make_float4(-3.4e38f, -3.4e38f, -3.4e38f, -3.4e38f);
                float4 sm = make_float4(0.f, 0.f, 0.f, 0.f);
                #pragma unroll
                for (int r = 0; r < 16; r++) {
                    float4 v = reinterpret_cast<const float4*>(token + (size_t)ro[r])[c];
                    mx.x = fmaxf(mx.x, v.x); mx.y = fmaxf(mx.y, v.y);
                    mx.z = fmaxf(mx.z, v.z); mx.w = fmaxf(mx.w, v.w);
                    sm.x += v.x; sm.y += v.y; sm.z += v.z; sm.w += v.w;
                }
                sm.x *= (1.f/16.f); sm.y *= (1.f/16.f);
                sm.z *= (1.f/16.f); sm.w *= (1.f/16.f);
                int kt = c >> 4, j = c & 15;
                int row0 = bsl * 2, row1 = row0 + 1;
                uint32_t base = kt * 4096;
                uint32_t o0 = base + row0 * 128 + ((((j >> 1) ^ (row0 & 7))) << 4) + ((j & 1) << 3);
                uint32_t o1 = base + row1 * 128 + ((((j >> 1) ^ (row1 & 7))) << 4) + ((j & 1) << 3);
                *reinterpret_cast<uint2*>(reinterpret_cast<char*>(smem_b) + o0) = f4_to_bf4(mx);
                *reinterpret_cast<uint2*>(reinterpret_cast<char*>(smem_b) + o1) = f4_to_bf4(sm);
            }
        }
        __syncthreads();

        // 32x64 GEMM: A full in smem, B TMA ring
        const int wm = warp >> 2;     // 0..1 (16 rows)
        const int wn = warp & 3;      // 0..3 (16 cols)
        float c[2][4];
        #pragma unroll
        for (int j = 0; j < 2; j++)
            #pragma unroll
            for (int r = 0; r < 4; r++) c[j][r] = 0.f;

        const int aRow = wm * 16 + (j4 & 1) * 8 + lr;
        const int aKj  = j4 >> 1;
        const int aSw  = aRow & 7;
        const uint32_t aByte = aRow * 128;
        const int bRow = wn * 16 + (j4 >> 1) * 8 + lr;
        const int bKj  = j4 & 1;
        const int bSw  = bRow & 7;
        const uint32_t bByte = bRow * 128;

        int cs = 0, cph = 0, ps = 0, pep = 0;
        for (int kt = 0; kt < 16; kt++) {
            mbar_wait(mb + cs * 8, cph);
            const uint32_t As = smem_s + kt * 4096;
            const uint32_t Bs = smem_s + MA_FULL + cs * MB_ST;

            #pragma unroll
            for (int step = 0; step < 4; step++) {
                const int cA = (2 * step + aKj) ^ aSw;
                const int cB = (2 * step + bKj) ^ bSw;
                uint32_t a[4], bb[4];
                LDMX4(a, As + aByte + (cA << 4));
                LDMX4(bb, Bs + bByte + (cB << 4));
                #pragma unroll
                for (int nt = 0; nt < 2; nt++)
                    MMA16816(c[nt], a, bb[nt*2], bb[nt*2+1]);
            }

            asm volatile("mbarrier.arrive.shared.b64 _, [%0];" :: "r"(mb + 24 + cs * 8) : "memory");

            if (tid == 0 && kt + 3 < 16) {
                mbar_wait(mb + 24 + ps * 8, pep);
                uint32_t fb = mb + ps * 8;
                asm volatile("mbarrier.arrive.expect_tx.shared.b64 _, [%0], %1;"
                             :: "r"(fb), "r"(MB_ST) : "memory");
                tma_2d(smem_s + MA_FULL + ps * MB_ST, &tmW64, (kt + 3) * 64, 192, fb);
                ps++; if (ps == 3) { ps = 0; pep ^= 1; }
            }
            cs++; if (cs == 3) { cs = 0; cph ^= 1; }
        }

        const int m0 = blockIdx.x * 32;
        const int rA = m0 + wm * 16 + g;
        #pragma unroll
        for (int nt = 0; nt < 2; nt++) {
            const int col = wn * 16 + nt * 8 + 2 * tg;
            *reinterpret_cast<float2*>(g_Ymi + (size_t)rA * 64 + col) =
                make_float2(c[nt][0], c[nt][1]);
            *reinterpret_cast<float2*>(g_Ymi + (size_t)(rA + 8) * 64 + col) =
                make_float2(c[nt][2], c[nt][3]);
        }
        __syncthreads();
        if (tid == 0) {
            __threadfence();
            atomicAdd(&g_miDone, 1);
        }
        return;
    }

    // ========== qkv: inline-gathered 32x192 GEMM + head ==========
    const int b = blockIdx.x - 16;
    // row offsets for this CTA's 32 A rows
    if (tid < 32) {
        int r  = tid & 15;
        int bs = b * 2 + (tid >> 4);
        int bb2 = bs >> 1, s = bs & 1;
        int l = r >> 3, k = r & 7;
        int ii = kw_idx[(bb2 * 2 + (1 - s)) * K_ + k];
        rowOff[tid] = (uint32_t)((((bb2 * 2 + s) * 2 + l) * S_ + ii) * D_);
    }
    __syncthreads();

    // A loader mapping: row = tid>>3, c8 = tid&7 (8 f32 = 2 float4 per stage)
    const int arow = tid >> 3;
    const int c8   = tid & 7;
    const float* rowBase = token + rowOff[arow];
    const uint32_t aStsOff = arow * 128 + ((c8 ^ (arow & 7)) << 4);

    #define A_LDG(kt, pre) { \
        const float4* src = reinterpret_cast<const float4*>(rowBase + (kt) * 64) + c8 * 2; \
        (pre)[0] = src[0]; (pre)[1] = src[1]; \
    }
    #define A_STS(kt, pre) { \
        uint2 lo = f4_to_bf4((pre)[0]); \
        uint2 hi = f4_to_bf4((pre)[1]); \
        uint4 d; d.x = lo.x; d.y = lo.y; d.z = hi.x; d.w = hi.y; \
        *reinterpret_cast<uint4*>(reinterpret_cast<char*>(smem_b) + ((kt) & 1) * QA_BUF + aStsOff) = d; \
    }

    float4 pre[2][2];
    A_LDG(0, pre[0]);
    A_STS(0, pre[0]);
    A_LDG(1, pre[1]);

    if (tid == 0) {
        #pragma unroll
        for (int s = 0; s < 3; s++) {
            uint32_t fb = mb + s * 8;
            asm volatile("mbarrier.arrive.expect_tx.shared.b64 _, [%0], %1;"
                         :: "r"(fb), "r"(QB_ST) : "memory");
            tma_2d(smem_s + QB_OFF + s * QB_ST, &tmW192, s * 64, 0, fb);
        }
    }
    __syncthreads();   // A stage 0 visible

    const int wm = warp >> 2;      // 0..1 -> bs_local
    const int wn = warp & 3;       // 0..3 (48 cols)

    float c[6][4];
    #pragma unroll
    for (int j = 0; j < 6; j++)
        #pragma unroll
        for (int r = 0; r < 4; r++) c[j][r] = 0.f;

    const int aRow = wm * 16 + (j4 & 1) * 8 + lr;
    const int aKj  = j4 >> 1;
    const int aSw  = aRow & 7;
    const uint32_t aByte = aRow * 128;
    const int bKj  = j4 & 1;
    const int bSw  = lr;
    uint32_t bByte[3];
    #pragma unroll
    for (int t = 0; t < 3; t++)
        bByte[t] = (wn * 48 + t * 16 + (j4 >> 1) * 8 + lr) * 128;

    int cs = 0, cph = 0, ps = 0, pep = 0;
    for (int kt = 0; kt < 16; kt++) {
        mbar_wait(mb + cs * 8, cph);
        const uint32_t As = smem_s + (kt & 1) * QA_BUF;
        const uint32_t Bs = smem_s + QB_OFF + cs * QB_ST;

        #pragma unroll
        for (int step = 0; step < 4; step++) {
            const int cA = (2 * step + aKj) ^ aSw;
            const int cB = (2 * step + bKj) ^ bSw;
            uint32_t a[4], bfr[3][4];
            LDMX4(a, As + aByte + (cA << 4));
            #pragma unroll
            for (int t = 0; t < 3; t++)
                LDMX4(bfr[t], Bs + bByte[t] + (cB << 4));
            #pragma unroll
            for (int nt = 0; nt < 6; nt++) {
                const uint32_t* bb = &bfr[nt >> 1][(nt & 1) * 2];
                MMA16816(c[nt], a, bb[0], bb[1]);
            }
        }

        asm volatile("mbarrier.arrive.shared.b64 _, [%0];" :: "r"(mb + 24 + cs * 8) : "memory");

        if (kt + 1 < 16) {
            A_STS(kt + 1, pre[(kt + 1) & 1]);
            if (kt + 2 < 16) { A_LDG(kt + 2, pre[(kt + 2) & 1]); }
        }

        if (tid == 0 && kt + 3 < 16) {
            mbar_wait(mb + 24 + ps * 8, pep);
            uint32_t fb = mb + ps * 8;
            asm volatile("mbarrier.arrive.expect_tx.shared.b64 _, [%0], %1;"
                         :: "r"(fb), "r"(QB_ST) : "memory");
            tma_2d(smem_s + QB_OFF + ps * QB_ST, &tmW192, (kt + 3) * 64, 0, fb);
            ps++; if (ps == 3) { ps = 0; pep ^= 1; }
        }
        cs++; if (cs == 3) { cs = 0; cph ^= 1; }
        __syncthreads();   // protect A double-buffer
    }

    // ---- epilogue: accumulators + bias -> head smem ----
    #pragma unroll
    for (int nt = 0; nt < 6; nt++) {
        const int col   = wn * 48 + nt * 8 + 2 * tg;
        const int which = col >> 6;
        const int hcol  = col & 63;
        const float* bp = (which == 0) ? q_b : (which == 1) ? k_b : v_b;
        float b0 = bp[hcol], b1 = bp[hcol + 1];
        float* d0 = hbuf + (size_t)((wm * 3 + which) * 16 + g) * PS + hcol;
        float* d1 = d0 + 8 * PS;
        d0[0] = c[nt][0] + b0; d0[1] = c[nt][1] + b1;
        d1[0] = c[nt][2] + b0; d1[1] = c[nt][3] + b1;
    }

    if (tid == 0) {
        int v;
        do {
            asm volatile("ld.global.acquire.gpu.b32 %0, [%1];" : "=r"(v) : "l"(&g_miDone));
        } while (v < 16);
    }
    __syncthreads();

    const float* q0 = hbuf + 0 * 16 * PS;
    const float* k0 = hbuf + 1 * 16 * PS;
    const float* v0 = hbuf + 2 * 16 * PS;
    const float* q1 = hbuf + 3 * 16 * PS;
    const float* k1 = hbuf + 4 * 16 * PS;
    const float* v1 = hbuf + 5 * 16 * PS;

    {
        int i = tid >> 6, h = tid & 63;
        sv[i][h] = g_Ymi[(size_t)(b * 4 + i) * 64 + h] + mi_b[h];
    }
    __syncthreads();

    #pragma unroll
    for (int e = tid; e < 512; e += 256) {
        int which = e >> 8, n = (e >> 4) & 15, m = e & 15;
        const float4* qq = reinterpret_cast<const float4*>((which ? q1 : q0) + n * PS);
        const float4* kk = reinterpret_cast<const float4*>((which ? k0 : k1) + m * PS);
        float4 acc = make_float4(0,0,0,0);
        #pragma unroll
        for (int t = 0; t < 16; t++) acc = fma4(qq[t], kk[t], acc);
        att[e] = hsum4(acc) * 0.125f;
    }
    {
        int i = tid >> 6, j = tid & 63;
        const float4* w = reinterpret_cast<const float4*>(inter_w + ((size_t)i * 64 + j) * 64);
        const float4* src = reinterpret_cast<const float4*>(sv[i >> 1]);
        float4 acc = make_float4(0,0,0,0);
        #pragma unroll
        for (int t = 0; t < 16; t++) acc = fma4(w[t], src[t], acc);
        aV[i][j] = inter_b[i * 64 + j] + hsum4(acc);
    }
    __syncthreads();

    #pragma unroll
    for (int f = tid; f < 512; f += 256) {
        int which = f >> 8, n = (f >> 4) & 15, h4 = f & 15;
        const float* vv = which ? v0 : v1;
        const float* am = att + which * 256 + n * 16;
        float4 s = make_float4(0,0,0,0);
        #pragma unroll
        for (int m = 0; m < 16; m++) {
            float a = am[m];
            float4 vm = *reinterpret_cast<const float4*>(vv + m * PS + 4 * h4);
            s.x = fmaf(a, vm.x, s.x); s.y = fmaf(a, vm.y, s.y);
            s.z = fmaf(a, vm.z, s.z); s.w = fmaf(a, vm.w, s.w);
        }
        *reinterpret_cast<float4*>((which ? e2s : e1s) + n * PS + 4 * h4) = s;
    }
    if (tid < 4) {
        int i = tid;
        const float4* av = reinterpret_cast<const float4*>(aV[i]);
        const float4* bv = reinterpret_cast<const float4*>(sv[2 + (i & 1)]);
        float4 d4 = make_float4(0,0,0,0), a4 = d4, b4 = d4;
        #pragma unroll
        for (int t = 0; t < 16; t++) {
            float4 a = av[t], bb = bv[t];
            d4 = fma4(a, bb, d4); a4 = fma4(a, a, a4); b4 = fma4(bb, bb, b4);
        }
        float na = fmaxf(sqrtf(hsum4(a4)), 1e-8f);
        float nb = fmaxf(sqrtf(hsum4(b4)), 1e-8f);
        feat[256 + i] = hsum4(d4) / (na * nb);
    }
    __syncthreads();

    if (tid < 128) {
        int which = tid >> 6, hh = tid & 63;
        const float* E = which ? e2s : e1s;
        float mx = -3.4e38f, sm = 0.f;
        #pragma unroll
        for (int n = 0; n < 16; n++) { float v = E[n * PS + hh]; mx = fmaxf(mx, v); sm += v; }
        feat[which * 128 + hh]      = mx;
        feat[which * 128 + 64 + hh] = sm * (1.f / 16.f);
    }
    feat[260 + tid] = sv[tid >> 6][tid & 63];
    __syncthreads();

    {
        int j = tid >> 2, part = tid & 3;
        int off = part * 128;
        int n4 = (part == 3) ? 33 : 32;
        const float4* w  = reinterpret_cast<const float4*>(fc0_w + (size_t)j * 516 + off);
        const float4* fr = reinterpret_cast<const float4*>(feat + off);
        float4 acc = make_float4(0,0,0,0);
        #pragma unroll 8
        for (int t = 0; t < n4; t++) acc = fma4(w[t], fr[t], acc);
        float s = hsum4(acc);
        s += __shfl_xor_sync(0xffffffff, s, 1);
        s += __shfl_xor_sync(0xffffffff, s, 2);
        if (part == 0) h1[j] = gelu_f(fc0_b[j] + s);
    }
    __syncthreads();

    if (tid == 0) {
        float l0 = fc1_b[0], l1 = fc1_b[1];
        #pragma unroll
        for (int j = 0; j < 64; j++) { l0 += h1[j] * fc1_w[j]; l1 += h1[j] * fc1_w[64 + j]; }
        l0 = gelu_f(l0); l1 = gelu_f(l1);
        float m = fmaxf(l0, l1);
        float ea = expf(l0 - m), eb = expf(l1 - m);
        float inv = 1.f / (ea + eb);
        out[b * 2 + 0] = ea * inv;
        out[b * 2 + 1] = eb * inv;
    }
}

// =====================================================================
typedef CUresult (*EncodeTiledFn)(
    CUtensorMap*, CUtensorMapDataType, cuuint32_t, void*,
    const cuuint64_t*, const cuuint64_t*, const cuuint32_t*, const cuuint32_t*,
    CUtensorMapInterleave, CUtensorMapSwizzle, CUtensorMapL2promotion,
    CUtensorMapFloatOOBfill);

static void make_map(EncodeTiledFn enc, CUtensorMap* tm, void* addr,
                     unsigned rows, unsigned boxRows) {
    cuuint64_t dims[2]    = {D_, rows};
    cuuint64_t strides[1] = {D_ * 2};
    cuuint32_t box[2]     = {64, boxRows};
    cuuint32_t es[2]      = {1, 1};
    enc(tm, CU_TENSOR_MAP_DATA_TYPE_BFLOAT16, 2, addr,
        dims, strides, box, es,
        CU_TENSOR_MAP_INTERLEAVE_NONE, CU_TENSOR_MAP_SWIZZLE_128B,
        CU_TENSOR_MAP_L2_PROMOTION_L2_128B, CU_TENSOR_MAP_FLOAT_OOB_FILL_NONE);
}

extern "C" void kernel_launch(void* const* d_in, const int* in_sizes, int n_in,
                              void* d_out, int out_size)
{
    const float* token   = (const float*)d_in[0];
    const int*   kw_idx  = (const int*)  d_in[1];
    const float* q_w     = (const float*)d_in[2];
    const float* q_b     = (const float*)d_in[3];
    const float* k_w     = (const float*)d_in[4];
    const float* k_b     = (const float*)d_in[5];
    const float* v_w     = (const float*)d_in[6];
    const float* v_b     = (const float*)d_in[7];
    const float* mi_w    = (const float*)d_in[8];
    const float* mi_b    = (const float*)d_in[9];
    const float* inter_w = (const float*)d_in[10];
    const float* inter_b = (const float*)d_in[11];
    const float* fc0_w   = (const float*)d_in[12];
    const float* fc0_b   = (const float*)d_in[13];
    const float* fc1_w   = (const float*)d_in[14];
    const float* fc1_b   = (const float*)d_in[15];
    float* out = (float*)d_out;

    void* encPtr = nullptr;
    cudaDriverEntryPointQueryResult qr;
    cudaGetDriverEntryPointByVersion("cuTensorMapEncodeTiled", &encPtr, 12000,
                                     cudaEnableDefault, &qr);
    EncodeTiledFn enc = (EncodeTiledFn)encPtr;

    void* wAddr = nullptr;
    cudaGetSymbolAddress(&wAddr, g_Wb);

    CUtensorMap tmW192, tmW64;
    make_map(enc, &tmW192, wAddr, 256, 192);
    make_map(enc, &tmW64,  wAddr, 256, 64);

    cudaFuncSetAttribute(fused_kernel,
                         cudaFuncAttributeMaxDynamicSharedMemorySize, DSMEM);

    wpack_kernel<<<32, 512>>>(q_w, k_w, v_w, mi_w);
    fused_kernel<<<144, 256, DSMEM>>>(tmW192, tmW64, token, kw_idx,
                                      q_b, k_b, v_b, mi_b,
                                      inter_w, inter_b,
                                      fc0_w, fc0_b, fc1_w, fc1_b, out);
}

// round 16
// speedup vs baseline: 1.1509x; 1.1509x over previous
#include <cuda_runtime.h>
#include <cuda.h>
#include <cuda_bf16.h>
#include <math.h>
#include <stdint.h>

// Problem constants
#define B_   128
#define S_   256
#define D_   1024
#define K_   8
#define L_   2

// -------- scratch (no allocations allowed) --------
__device__ uint16_t g_X16[(size_t)4096 * D_];  // gathered data rows, bf16
__device__ uint16_t g_Xp [(size_t)512 * D_];   // pooled rows bf16 (bs*2+{max,avg})
__device__ uint16_t g_Wb [(size_t)256 * D_];   // packed weights q|k|v|mi, bf16
__device__ float    g_Ymi [(size_t)512 * 64];  // mi projections
__device__ int      g_miDone;                  // mi-completion counter

__device__ __forceinline__ uint2 f4_to_bf4(float4 v) {
    __nv_bfloat162 lo = __floats2bfloat162_rn(v.x, v.y);
    __nv_bfloat162 hi = __floats2bfloat162_rn(v.z, v.w);
    uint2 r;
    r.x = *reinterpret_cast<uint32_t*>(&lo);
    r.y = *reinterpret_cast<uint32_t*>(&hi);
    return r;
}

// =====================================================================
// Kernel 1: gather (blocks 0..255, 512 thr) + weight pack (256..287)
//           + g_miDone reset
// =====================================================================
__global__ void __launch_bounds__(512)
gather_pack_kernel(const float* __restrict__ token,
                   const int* __restrict__ kw_idx,
                   const float* __restrict__ wq, const float* __restrict__ wk,
                   const float* __restrict__ wv, const float* __restrict__ wmi)
{
    int tid = threadIdx.x;
    if (blockIdx.x >= 256) {
        if (blockIdx.x == 256 && tid == 0) g_miDone = 0;
        int f4base = (blockIdx.x - 256) * 2048 + tid;
        #pragma unroll
        for (int i = 0; i < 4; i++) {
            int f4 = f4base + i * 512;
            int wsel = f4 >> 14;
            const float* W = (wsel == 0) ? wq : (wsel == 1) ? wk :
                             (wsel == 2) ? wv : wmi;
            float4 v = reinterpret_cast<const float4*>(W)[f4 & 16383];
            reinterpret_cast<uint2*>(g_Wb)[f4] = f4_to_bf4(v);
        }
        return;
    }

    __shared__ int idx[K_];
    __shared__ float4 pmax[2][256];
    __shared__ float4 psum[2][256];

    int bs = blockIdx.x;
    int b = bs >> 1, s = bs & 1;
    if (tid < K_)
        idx[tid] = kw_idx[(b * 2 + (1 - s)) * K_ + tid];
    __syncthreads();

    int col = tid & 255;
    int rp  = tid >> 8;
    const float* tbase = token + (((size_t)b * 2 + s) * L_ + rp) * S_ * D_;
    uint16_t* Xrow = g_X16 + (size_t)bs * 16 * D_;

    float4 mx = make_float4(-3.4e38f, -3.4e38f, -3.4e38f, -3.4e38f);
    float4 sm = make_float4(0.f, 0.f, 0.f, 0.f);

    #pragma unroll
    for (int j = 0; j < 8; j++) {
        int r = rp * 8 + j;
        float4 v = reinterpret_cast<const float4*>(tbase + (size_t)idx[j] * D_)[col];
        reinterpret_cast<uint2*>(Xrow + (size_t)r * D_)[col] = f4_to_bf4(v);
        mx.x = fmaxf(mx.x, v.x); mx.y = fmaxf(mx.y, v.y);
        mx.z = fmaxf(mx.z, v.z); mx.w = fmaxf(mx.w, v.w);
        sm.x += v.x; sm.y += v.y; sm.z += v.z; sm.w += v.w;
    }
    pmax[rp][col] = mx;
    psum[rp][col] = sm;
    __syncthreads();

    if (tid < 256) {
        float4 m0 = pmax[0][col], m1 = pmax[1][col];
        float4 s0 = psum[0][col], s1 = psum[1][col];
        float4 M, S;
        M.x = fmaxf(m0.x, m1.x); M.y = fmaxf(m0.y, m1.y);
        M.z = fmaxf(m0.z, m1.z); M.w = fmaxf(m0.w, m1.w);
        S.x = (s0.x + s1.x) * (1.f/16.f);
        S.y = (s0.y + s1.y) * (1.f/16.f);
        S.z = (s0.z + s1.z) * (1.f/16.f);
        S.w = (s0.w + s1.w) * (1.f/16.f);
        uint16_t* Xp = g_Xp + (size_t)bs * 2 * D_;
        reinterpret_cast<uint2*>(Xp)[col]      = f4_to_bf4(M);
        reinterpret_cast<uint2*>(Xp + D_)[col] = f4_to_bf4(S);
    }
}

// =====================================================================
// Kernel 2: FUSED GEMM + head.
//  blocks 0..15  : mi — 32x64 tile over g_Xp -> g_Ymi, then flag.
//  blocks 16..143: qkv — 32x192 tile (batch b = bid-16) -> head inline.
// =====================================================================
#define QA_ST  4096
#define QB_ST  24576
#define QSTG   (QA_ST + QB_ST)        // 28672
#define MA_ST  4096                    // 32 rows
#define MB_ST  8192                    // 64 rows
#define MSTG   (MA_ST + MB_ST)         // 12288
#define GEMM_SMEM (3 * QSTG)           // 86016 dynamic

#define PS 68   // padded head row stride (floats)

__device__ __forceinline__ void mbar_wait(uint32_t mbar, int phase) {
    asm volatile(
        "{\n\t.reg .pred P;\n"
        "W%=:\n\t"
        "mbarrier.try_wait.parity.acquire.cta.shared::cta.b64 P, [%0], %1, 0x989680;\n\t"
        "@P bra D%=;\n\t"
        "bra W%=;\n"
        "D%=:\n\t}"
        :: "r"(mbar), "r"(phase) : "memory");
}

__device__ __forceinline__ void tma_2d(uint32_t dst, const CUtensorMap* tm,
                                       int x, int y, uint32_t mbar) {
    asm volatile(
        "cp.async.bulk.tensor.2d.shared::cta.global.tile.mbarrier::complete_tx::bytes "
        "[%0], [%1, {%2, %3}], [%4];"
        :: "r"(dst), "l"(tm), "r"(x), "r"(y), "r"(mbar) : "memory");
}

#define LDMX4(dst, addr) \
    asm volatile("ldmatrix.sync.aligned.m8n8.x4.shared.b16 {%0,%1,%2,%3}, [%4];" \
                 : "=r"((dst)[0]), "=r"((dst)[1]), "=r"((dst)[2]), "=r"((dst)[3]) : "r"(addr))

#define MMA16816(c, a, b0r, b1r) \
    asm volatile("mma.sync.aligned.m16n8k16.row.col.f32.bf16.bf16.f32 " \
                 "{%0,%1,%2,%3}, {%4,%5,%6,%7}, {%8,%9}, {%0,%1,%2,%3};" \
                 : "+f"((c)[0]), "+f"((c)[1]), "+f"((c)[2]), "+f"((c)[3]) \
                 : "r"((a)[0]), "r"((a)[1]), "r"((a)[2]), "r"((a)[3]), \
                   "r"(b0r), "r"(b1r))

__device__ __forceinline__ float gelu_f(float x) {
    return 0.5f * x * (1.0f + erff(x * 0.70710678118654752440f));
}
__device__ __forceinline__ float4 fma4(float4 a, float4 b, float4 c) {
    return make_float4(fmaf(a.x,b.x,c.x), fmaf(a.y,b.y,c.y),
                       fmaf(a.z,b.z,c.z), fmaf(a.w,b.w,c.w));
}
__device__ __forceinline__ float hsum4(float4 a) { return (a.x+a.y)+(a.z+a.w); }

__global__ void __launch_bounds__(256, 1)
gemm_head_kernel(const __grid_constant__ CUtensorMap tmX16,
                 const __grid_constant__ CUtensorMap tmXp,
                 const __grid_constant__ CUtensorMap tmW192,
                 const __grid_constant__ CUtensorMap tmW64,
                 const float* __restrict__ q_b, const float* __restrict__ k_b,
                 const float* __restrict__ v_b, const float* __restrict__ mi_b,
                 const float* __restrict__ inter_w, const float* __restrict__ inter_b,
                 const float* __restrict__ fc0_w, const float* __restrict__ fc0_b,
                 const float* __restrict__ fc1_w, const float* __restrict__ fc1_b,
                 float* __restrict__ out)
{
    extern __shared__ __align__(1024) uint16_t smem_b[];
    __shared__ __align__(8) uint64_t mbar_s[6];
    __shared__ __align__(16) float hbuf[6 * 16 * PS];
    __shared__ __align__(16) float e1s[16*PS], e2s[16*PS];
    __shared__ __align__(16) float att[512];
    __shared__ __align__(16) float sv[4][64];
    __shared__ __align__(16) float aV[4][64];
    __shared__ __align__(16) float feat[520];
    __shared__ float h1[64];

    const uint32_t smem_s = (uint32_t)__cvta_generic_to_shared(smem_b);
    const uint32_t mb     = (uint32_t)__cvta_generic_to_shared(mbar_s);

    const int tid  = threadIdx.x;
    const int lane = tid & 31;
    const int warp = tid >> 5;
    const bool isMi = (blockIdx.x < 16);

    if (tid == 0) {
        #pragma unroll
        for (int s = 0; s < 3; s++) {
            asm volatile("mbarrier.init.shared.b64 [%0], %1;" :: "r"(mb + s * 8), "r"(1) : "memory");
            asm volatile("mbarrier.init.shared.b64 [%0], %1;" :: "r"(mb + 24 + s * 8), "r"(256) : "memory");
        }
    }
    __syncthreads();

    const int j4 = lane >> 3;
    const int lr = lane & 7;
    const int g  = lane >> 2;
    const int tg = lane & 3;

    if (isMi) {
        // ---------- mi: 32x64 tile over pooled rows ----------
        const int m0 = blockIdx.x * 32;
        const int wm = warp >> 2;      // 0..1 (16 rows)
        const int wn = warp & 3;       // 0..3 (16 cols)

        if (tid == 0) {
            #pragma unroll
            for (int s = 0; s < 3; s++) {
                uint32_t fb = mb + s * 8;
                asm volatile("mbarrier.arrive.expect_tx.shared.b64 _, [%0], %1;"
                             :: "r"(fb), "r"(MSTG) : "memory");
                uint32_t base = smem_s + s * MSTG;
                tma_2d(base,         &tmXp, s * 64, m0, fb);
                tma_2d(base + MA_ST, &tmW64, s * 64, 192, fb);
            }
        }

        float c[2][4];
        #pragma unroll
        for (int j = 0; j < 2; j++)
            #pragma unroll
            for (int r = 0; r < 4; r++) c[j][r] = 0.f;

        const int aRow = wm * 16 + (j4 & 1) * 8 + lr;
        const int aKj  = j4 >> 1;
        const int aSw  = aRow & 7;
        const uint32_t aByte = aRow * 128;
        const int bRow = wn * 16 + (j4 >> 1) * 8 + lr;
        const int bKj  = j4 & 1;
        const int bSw  = bRow & 7;
        const uint32_t bByte = bRow * 128;

        int cs = 0, cph = 0, ps = 0, pep = 0;
        for (int kt = 0; kt < 16; kt++) {
            mbar_wait(mb + cs * 8, cph);
            const uint32_t As = smem_s + cs * MSTG;
            const uint32_t Bs = As + MA_ST;

            #pragma unroll
            for (int step = 0; step < 4; step++) {
                const int cA = (2 * step + aKj) ^ aSw;
                const int cB = (2 * step + bKj) ^ bSw;
                uint32_t a[4], bb[4];
                LDMX4(a, As + aByte + (cA << 4));
                LDMX4(bb, Bs + bByte + (cB << 4));
                #pragma unroll
                for (int nt = 0; nt < 2; nt++)
                    MMA16816(c[nt], a, bb[nt*2], bb[nt*2+1]);
            }

            asm volatile("mbarrier.arrive.shared.b64 _, [%0];" :: "r"(mb + 24 + cs * 8) : "memory");

            if (tid == 0 && kt + 3 < 16) {
                mbar_wait(mb + 24 + ps * 8, pep);
                uint32_t fb = mb + ps * 8;
                asm volatile("mbarrier.arrive.expect_tx.shared.b64 _, [%0], %1;"
                             :: "r"(fb), "r"(MSTG) : "memory");
                uint32_t base = smem_s + ps * MSTG;
                tma_2d(base,         &tmXp, (kt + 3) * 64, m0, fb);
                tma_2d(base + MA_ST, &tmW64, (kt + 3) * 64, 192, fb);
                ps++; if (ps == 3) { ps = 0; pep ^= 1; }
            }
            cs++; if (cs == 3) { cs = 0; cph ^= 1; }
        }

        const int rA = m0 + wm * 16 + g;
        #pragma unroll
        for (int nt = 0; nt < 2; nt++) {
            const int col = wn * 16 + nt * 8 + 2 * tg;
            *reinterpret_cast<float2*>(g_Ymi + (size_t)rA * 64 + col) =
                make_float2(c[nt][0], c[nt][1]);
            *reinterpret_cast<float2*>(g_Ymi + (size_t)(rA + 8) * 64 + col) =
                make_float2(c[nt][2], c[nt][3]);
        }
        __syncthreads();
        if (tid == 0) {
            __threadfence();
            atomicAdd(&g_miDone, 1);
        }
        return;
    }

    // ---------- qkv: 32x192 tile + inline head (batch b = bid-16) ----------
    const int b  = blockIdx.x - 16;
    const int m0 = b * 32;
    const int wm = warp >> 2;      // 0..1 -> bs_local
    const int wn = warp & 3;       // 0..3 (48 cols)

    if (tid == 0) {
        #pragma unroll
        for (int s = 0; s < 3; s++) {
            uint32_t fb = mb + s * 8;
            asm volatile("mbarrier.arrive.expect_tx.shared.b64 _, [%0], %1;"
                         :: "r"(fb), "r"(QSTG) : "memory");
            uint32_t base = smem_s + s * QSTG;
            tma_2d(base,         &tmX16, s * 64, m0, fb);
            tma_2d(base + QA_ST, &tmW192, s * 64, 0, fb);
        }
    }

    float c[6][4];
    #pragma unroll
    for (int j = 0; j < 6; j++)
        #pragma unroll
        for (int r = 0; r < 4; r++) c[j][r] = 0.f;

    const int aRow = wm * 16 + (j4 & 1) * 8 + lr;
    const int aKj  = j4 >> 1;
    const int aSw  = aRow & 7;
    const uint32_t aByte = aRow * 128;
    const int bKj  = j4 & 1;
    const int bSw  = lr;
    uint32_t bByte[3];
    #pragma unroll
    for (int t = 0; t < 3; t++)
        bByte[t] = (wn * 48 + t * 16 + (j4 >> 1) * 8 + lr) * 128;

    int cs = 0, cph = 0, ps = 0, pep = 0;
    for (int kt = 0; kt < 16; kt++) {
        mbar_wait(mb + cs * 8, cph);
        const uint32_t As = smem_s + cs * QSTG;
        const uint32_t Bs = As + QA_ST;

        #pragma unroll
        for (int step = 0; step < 4; step++) {
            const int cA = (2 * step + aKj) ^ aSw;
            const int cB = (2 * step + bKj) ^ bSw;
            uint32_t a[4], bfr[3][4];
            LDMX4(a, As + aByte + (cA << 4));
            #pragma unroll
            for (int t = 0; t < 3; t++)
                LDMX4(bfr[t], Bs + bByte[t] + (cB << 4));
            #pragma unroll
            for (int nt = 0; nt < 6; nt++) {
                const uint32_t* bb = &bfr[nt >> 1][(nt & 1) * 2];
                MMA16816(c[nt], a, bb[0], bb[1]);
            }
        }

        asm volatile("mbarrier.arrive.shared.b64 _, [%0];" :: "r"(mb + 24 + cs * 8) : "memory");

        if (tid == 0 && kt + 3 < 16) {
            mbar_wait(mb + 24 + ps * 8, pep);
            uint32_t fb = mb + ps * 8;
            asm volatile("mbarrier.arrive.expect_tx.shared.b64 _, [%0], %1;"
                         :: "r"(fb), "r"(QSTG) : "memory");
            uint32_t base = smem_s + ps * QSTG;
            tma_2d(base,         &tmX16, (kt + 3) * 64, m0, fb);
            tma_2d(base + QA_ST, &tmW192, (kt + 3) * 64, 0, fb);
            ps++; if (ps == 3) { ps = 0; pep ^= 1; }
        }
        cs++; if (cs == 3) { cs = 0; cph ^= 1; }
    }

    // ---- epilogue: accumulators + bias -> head smem ----
    #pragma unroll
    for (int nt = 0; nt < 6; nt++) {
        const int col   = wn * 48 + nt * 8 + 2 * tg;
        const int which = col >> 6;
        const int hcol  = col & 63;
        const float* bp = (which == 0) ? q_b : (which == 1) ? k_b : v_b;
        float b0 = bp[hcol], b1 = bp[hcol + 1];
        float* d0 = hbuf + (size_t)((wm * 3 + which) * 16 + g) * PS + hcol;
        float* d1 = d0 + 8 * PS;
        d0[0] = c[nt][0] + b0; d0[1] = c[nt][1] + b1;
        d1[0] = c[nt][2] + b0; d1[1] = c[nt][3] + b1;
    }

    // ---- wait for mi results ----
    if (tid == 0) {
        int v;
        do {
            asm volatile("ld.global.acquire.gpu.b32 %0, [%1];" : "=r"(v) : "l"(&g_miDone));
        } while (v < 16);
    }
    __syncthreads();

    const float* q0 = hbuf + 0 * 16 * PS;
    const float* k0 = hbuf + 1 * 16 * PS;
    const float* v0 = hbuf + 2 * 16 * PS;
    const float* q1 = hbuf + 3 * 16 * PS;
    const float* k1 = hbuf + 4 * 16 * PS;
    const float* v1 = hbuf + 5 * 16 * PS;

    {
        int i = tid >> 6, h = tid & 63;
        sv[i][h] = g_Ymi[(size_t)(b * 4 + i) * 64 + h] + mi_b[h];
    }
    __syncthreads();

    #pragma unroll
    for (int e = tid; e < 512; e += 256) {
        int which = e >> 8, n = (e >> 4) & 15, m = e & 15;
        const float4* qq = reinterpret_cast<const float4*>((which ? q1 : q0) + n * PS);
        const float4* kk = reinterpret_cast<const float4*>((which ? k0 : k1) + m * PS);
        float4 acc = make_float4(0,0,0,0);
        #pragma unroll
        for (int t = 0; t < 16; t++) acc = fma4(qq[t], kk[t], acc);
        att[e] = hsum4(acc) * 0.125f;
    }
    {
        int i = tid >> 6, j = tid & 63;
        const float4* w = reinterpret_cast<const float4*>(inter_w + ((size_t)i * 64 + j) * 64);
        const float4* src = reinterpret_cast<const float4*>(sv[i >> 1]);
        float4 acc = make_float4(0,0,0,0);
        #pragma unroll
        for (int t = 0; t < 16; t++) acc = fma4(w[t], src[t], acc);
        aV[i][j] = inter_b[i * 64 + j] + hsum4(acc);
    }
    __syncthreads();

    #pragma unroll
    for (int f = tid; f < 512; f += 256) {
        int which = f >> 8, n = (f >> 4) & 15, h4 = f & 15;
        const float* vv = which ? v0 : v1;
        const float* am = att + which * 256 + n * 16;
        float4 s = make_float4(0,0,0,0);
        #pragma unroll
        for (int m = 0; m < 16; m++) {
            float a = am[m];
            float4 vm = *reinterpret_cast<const float4*>(vv + m * PS + 4 * h4);
            s.x = fmaf(a, vm.x, s.x); s.y = fmaf(a, vm.y, s.y);
            s.z = fmaf(a, vm.z, s.z); s.w = fmaf(a, vm.w, s.w);
        }
        *reinterpret_cast<float4*>((which ? e2s : e1s) + n * PS + 4 * h4) = s;
    }
    if (tid < 4) {
        int i = tid;
        const float4* av = reinterpret_cast<const float4*>(aV[i]);
        const float4* bv = reinterpret_cast<const float4*>(sv[2 + (i & 1)]);
        float4 d4 = make_float4(0,0,0,0), a4 = d4, b4 = d4;
        #pragma unroll
        for (int t = 0; t < 16; t++) {
            float4 a = av[t], bb = bv[t];
            d4 = fma4(a, bb, d4); a4 = fma4(a, a, a4); b4 = fma4(bb, bb, b4);
        }
        float na = fmaxf(sqrtf(hsum4(a4)), 1e-8f);
        float nb = fmaxf(sqrtf(hsum4(b4)), 1e-8f);
        feat[256 + i] = hsum4(d4) / (na * nb);
    }
    __syncthreads();

    if (tid < 128) {
        int which = tid >> 6, hh = tid & 63;
        const float* E = which ? e2s : e1s;
        float mx = -3.4e38f, sm = 0.f;
        #pragma unroll
        for (int n = 0; n < 16; n++) { float v = E[n * PS + hh]; mx = fmaxf(mx, v); sm += v; }
        feat[which * 128 + hh]      = mx;
        feat[which * 128 + 64 + hh] = sm * (1.f / 16.f);
    }
    feat[260 + tid] = sv[tid >> 6][tid & 63];
    __syncthreads();

    {
        int j = tid >> 2, part = tid & 3;
        int off = part * 128;
        int n4 = (part == 3) ? 33 : 32;
        const float4* w  = reinterpret_cast<const float4*>(fc0_w + (size_t)j * 516 + off);
        const float4* fr = reinterpret_cast<const float4*>(feat + off);
        float4 acc = make_float4(0,0,0,0);
        #pragma unroll 8
        for (int t = 0; t < n4; t++) acc = fma4(w[t], fr[t], acc);
        float s = hsum4(acc);
        s += __shfl_xor_sync(0xffffffff, s, 1);
        s += __shfl_xor_sync(0xffffffff, s, 2);
        if (part == 0) h1[j] = gelu_f(fc0_b[j] + s);
    }
    __syncthreads();

    if (tid == 0) {
        float l0 = fc1_b[0], l1 = fc1_b[1];
        #pragma unroll
        for (int j = 0; j < 64; j++) { l0 += h1[j] * fc1_w[j]; l1 += h1[j] * fc1_w[64 + j]; }
        l0 = gelu_f(l0); l1 = gelu_f(l1);
        float m = fmaxf(l0, l1);
        float ea = expf(l0 - m), eb = expf(l1 - m);
        float inv = 1.f / (ea + eb);
        out[b * 2 + 0] = ea * inv;
        out[b * 2 + 1] = eb * inv;
    }
}

// =====================================================================
typedef CUresult (*EncodeTiledFn)(
    CUtensorMap*, CUtensorMapDataType, cuuint32_t, void*,
    const cuuint64_t*, const cuuint64_t*, const cuuint32_t*, const cuuint32_t*,
    CUtensorMapInterleave, CUtensorMapSwizzle, CUtensorMapL2promotion,
    CUtensorMapFloatOOBfill);

static void make_map(EncodeTiledFn enc, CUtensorMap* tm, void* addr,
                     unsigned rows, unsigned boxRows) {
    cuuint64_t dims[2]    = {D_, rows};
    cuuint64_t strides[1] = {D_ * 2};
    cuuint32_t box[2]     = {64, boxRows};
    cuuint32_t es[2]      = {1, 1};
    enc(tm, CU_TENSOR_MAP_DATA_TYPE_BFLOAT16, 2, addr,
        dims, strides, box, es,
        CU_TENSOR_MAP_INTERLEAVE_NONE, CU_TENSOR_MAP_SWIZZLE_128B,
        CU_TENSOR_MAP_L2_PROMOTION_L2_128B, CU_TENSOR_MAP_FLOAT_OOB_FILL_NONE);
}

extern "C" void kernel_launch(void* const* d_in, const int* in_sizes, int n_in,
                              void* d_out, int out_size)
{
    const float* token   = (const float*)d_in[0];
    const int*   kw_idx  = (const int*)  d_in[1];
    const float* q_w     = (const float*)d_in[2];
    const float* q_b     = (const float*)d_in[3];
    const float* k_w     = (const float*)d_in[4];
    const float* k_b     = (const float*)d_in[5];
    const float* v_w     = (const float*)d_in[6];
    const float* v_b     = (const float*)d_in[7];
    const float* mi_w    = (const float*)d_in[8];
    const float* mi_b    = (const float*)d_in[9];
    const float* inter_w = (const float*)d_in[10];
    const float* inter_b = (const float*)d_in[11];
    const float* fc0_w   = (const float*)d_in[12];
    const float* fc0_b   = (const float*)d_in[13];
    const float* fc1_w   = (const float*)d_in[14];
    const float* fc1_b   = (const float*)d_in[15];
    float* out = (float*)d_out;

    void* encPtr = nullptr;
    cudaDriverEntryPointQueryResult qr;
    cudaGetDriverEntryPointByVersion("cuTensorMapEncodeTiled", &encPtr, 12000,
                                     cudaEnableDefault, &qr);
    EncodeTiledFn enc = (EncodeTiledFn)encPtr;

    void *x16Addr = nullptr, *xpAddr = nullptr, *wAddr = nullptr;
    cudaGetSymbolAddress(&x16Addr, g_X16);
    cudaGetSymbolAddress(&xpAddr,  g_Xp);
    cudaGetSymbolAddress(&wAddr,   g_Wb);

    CUtensorMap tmX16, tmXp, tmW192, tmW64;
    make_map(enc, &tmX16, x16Addr, 4096, 32);
    make_map(enc, &tmXp,  xpAddr,  512,  32);
    make_map(enc, &tmW192, wAddr,  256,  192);
    make_map(enc, &tmW64,  wAddr,  256,  64);

    cudaFuncSetAttribute(gemm_head_kernel,
                         cudaFuncAttributeMaxDynamicSharedMemorySize, GEMM_SMEM);

    gather_pack_kernel<<<256 + 32, 512>>>(token, kw_idx, q_w, k_w, v_w, mi_w);
    gemm_head_kernel<<<144, 256, GEMM_SMEM>>>(tmX16, tmXp, tmW192, tmW64,
                                              q_b, k_b, v_b, mi_b,
                                              inter_w, inter_b,
                                              fc0_w, fc0_b, fc1_w, fc1_b, out);
}